// round 4
// baseline (speedup 1.0000x reference)
#include <cuda_runtime.h>
#include <math.h>
#include <stdint.h>
#include <stddef.h>

typedef unsigned long long u64;

#define NB   100
#define TT   512
#define IND  256
#define HD   1024
#define H3   3072
#define NDB  (HD * NB)   // 102400

// ---------------- scratch ----------------
__device__ float g_xp [(size_t)NB * TT * H3];   // xp [b][t][g]; later reused as S [u][(d,b)]
__device__ float g_xpt[(size_t)TT * H3 * NB];   // xp transposed [t][g][b]
__device__ float g_hst[(size_t)TT * HD * NB];   // h states [t][d][b]
__device__ float g_vt  [NDB];
__device__ float g_hpt [NDB];
__device__ float g_innert[NDB];
__device__ float g_catv8[HD * 8];
__device__ float g_hp2t [HD * 8];
__device__ float g_catot[HD * 5];
__device__ float g_as[NB];
__device__ float g_ad[NB];
__device__ float g_as2[8];
__device__ float g_ad2[8];
__device__ float g_fint[H3 * NB];
__device__ float g_ft  [HD * NB];
__device__ unsigned g_cnt;
__device__ unsigned g_gen;

// ---------------- f32x2 helpers ----------------
__device__ __forceinline__ u64 bcast2(float x) {
    u64 r; unsigned u = __float_as_uint(x);
    asm("mov.b64 %0, {%1, %1};" : "=l"(r) : "r"(u));
    return r;
}
__device__ __forceinline__ void fma2(u64& d, u64 a, u64 b) {
    asm("fma.rn.f32x2 %0, %1, %2, %0;" : "+l"(d) : "l"(a), "l"(b));
}
__device__ __forceinline__ float2 unpk(u64 v) {
    unsigned lo, hi;
    asm("mov.b64 {%0, %1}, %2;" : "=r"(lo), "=r"(hi) : "l"(v));
    return make_float2(__uint_as_float(lo), __uint_as_float(hi));
}
__device__ __forceinline__ float sigf(float x) { return 1.f / (1.f + expf(-x)); }

// =================================================================
// SGEMM NT: C[M,N] = A[M,K] @ B[N,K]^T + colbias[N]
// =================================================================
__global__ __launch_bounds__(256) void gemm_nt(
    const float* __restrict__ A, const float* __restrict__ B,
    const float* __restrict__ colbias, float* __restrict__ C,
    int M, int N, int K, int act)
{
    __shared__ float As[16][128];
    __shared__ float Bs[16][128];
    int tid = threadIdx.x;
    int tx = tid & 15, ty = tid >> 4;
    int row0 = blockIdx.y * 128, col0 = blockIdx.x * 128;

    u64 acc[8][4];
#pragma unroll
    for (int i = 0; i < 8; i++)
#pragma unroll
        for (int j = 0; j < 4; j++) acc[i][j] = 0ull;

    int lr = tid >> 2, lc = tid & 3;
    for (int k0 = 0; k0 < K; k0 += 16) {
#pragma unroll
        for (int p = 0; p < 2; p++) {
            int r = lr + p * 64, gr = row0 + r;
            float4 v = make_float4(0.f, 0.f, 0.f, 0.f);
            if (gr < M) v = *(const float4*)(A + (size_t)gr * K + k0 + lc * 4);
            As[lc*4+0][r] = v.x; As[lc*4+1][r] = v.y; As[lc*4+2][r] = v.z; As[lc*4+3][r] = v.w;
        }
#pragma unroll
        for (int p = 0; p < 2; p++) {
            int r = lr + p * 64, gc = col0 + r;
            float4 v = make_float4(0.f, 0.f, 0.f, 0.f);
            if (gc < N) v = *(const float4*)(B + (size_t)gc * K + k0 + lc * 4);
            Bs[lc*4+0][r] = v.x; Bs[lc*4+1][r] = v.y; Bs[lc*4+2][r] = v.z; Bs[lc*4+3][r] = v.w;
        }
        __syncthreads();
#pragma unroll
        for (int kk = 0; kk < 16; kk++) {
            float a[8];
            *(float4*)&a[0] = *(const float4*)&As[kk][ty * 8];
            *(float4*)&a[4] = *(const float4*)&As[kk][ty * 8 + 4];
            u64 b4[4];
#pragma unroll
            for (int j = 0; j < 4; j++) b4[j] = *(const u64*)&Bs[kk][tx * 8 + 2 * j];
#pragma unroll
            for (int i = 0; i < 8; i++) {
                u64 ai = bcast2(a[i]);
#pragma unroll
                for (int j = 0; j < 4; j++) fma2(acc[i][j], ai, b4[j]);
            }
        }
        __syncthreads();
    }
#pragma unroll
    for (int i = 0; i < 8; i++) {
        int gm = row0 + ty * 8 + i;
        if (gm >= M) continue;
#pragma unroll
        for (int j = 0; j < 4; j++) {
            float2 c2 = unpk(acc[i][j]);
            int gn = col0 + tx * 8 + 2 * j;
            float v0 = c2.x, v1 = c2.y;
            if (colbias) { v0 += colbias[gn]; v1 += colbias[gn + 1]; }
            if (act == 1) { v0 = fmaxf(v0, 0.f); v1 = fmaxf(v1, 0.f); }
            if (gn < N)     C[(size_t)gm * N + gn]     = v0;
            if (gn + 1 < N) C[(size_t)gm * N + gn + 1] = v1;
        }
    }
}

// =================================================================
// SGEMM NN: C[M,N] = A[M,K] @ B[K,N] (+ rowbias[M]) (+relu). N%4==0.
// =================================================================
__global__ __launch_bounds__(256) void gemm_nn(
    const float* __restrict__ A, const float* __restrict__ B,
    const float* __restrict__ rowbias, float* __restrict__ C,
    int M, int N, int K, int act)
{
    __shared__ float As[16][128];
    __shared__ float Bs[16][128];
    int tid = threadIdx.x;
    int tx = tid & 15, ty = tid >> 4;
    int row0 = blockIdx.y * 128, col0 = blockIdx.x * 128;

    u64 acc[8][4];
#pragma unroll
    for (int i = 0; i < 8; i++)
#pragma unroll
        for (int j = 0; j < 4; j++) acc[i][j] = 0ull;

    int lr = tid >> 2, lc = tid & 3;
    int br = tid >> 5, bc = tid & 31;
    for (int k0 = 0; k0 < K; k0 += 16) {
#pragma unroll
        for (int p = 0; p < 2; p++) {
            int r = lr + p * 64, gr = row0 + r;
            float4 v = make_float4(0.f, 0.f, 0.f, 0.f);
            if (gr < M) v = *(const float4*)(A + (size_t)gr * K + k0 + lc * 4);
            As[lc*4+0][r] = v.x; As[lc*4+1][r] = v.y; As[lc*4+2][r] = v.z; As[lc*4+3][r] = v.w;
        }
#pragma unroll
        for (int p = 0; p < 2; p++) {
            int k = br + p * 8;
            int gc = col0 + bc * 4;
            float4 v = make_float4(0.f, 0.f, 0.f, 0.f);
            if (gc < N) v = *(const float4*)(B + (size_t)(k0 + k) * N + gc);
            *(float4*)&Bs[k][bc * 4] = v;
        }
        __syncthreads();
#pragma unroll
        for (int kk = 0; kk < 16; kk++) {
            float a[8];
            *(float4*)&a[0] = *(const float4*)&As[kk][ty * 8];
            *(float4*)&a[4] = *(const float4*)&As[kk][ty * 8 + 4];
            u64 b4[4];
#pragma unroll
            for (int j = 0; j < 4; j++) b4[j] = *(const u64*)&Bs[kk][tx * 8 + 2 * j];
#pragma unroll
            for (int i = 0; i < 8; i++) {
                u64 ai = bcast2(a[i]);
#pragma unroll
                for (int j = 0; j < 4; j++) fma2(acc[i][j], ai, b4[j]);
            }
        }
        __syncthreads();
    }
#pragma unroll
    for (int i = 0; i < 8; i++) {
        int gm = row0 + ty * 8 + i;
        if (gm >= M) continue;
        float rb = rowbias ? rowbias[gm] : 0.f;
#pragma unroll
        for (int j = 0; j < 4; j++) {
            float2 c2 = unpk(acc[i][j]);
            int gn = col0 + tx * 8 + 2 * j;
            float v0 = c2.x + rb, v1 = c2.y + rb;
            if (act == 1) { v0 = fmaxf(v0, 0.f); v1 = fmaxf(v1, 0.f); }
            if (gn < N)     C[(size_t)gm * N + gn]     = v0;
            if (gn + 1 < N) C[(size_t)gm * N + gn + 1] = v1;
        }
    }
}

// =================================================================
// Transpose xp[b][t][g] -> xpt[t][g][b]. Block = (t, 32-g chunk).
// =================================================================
__global__ __launch_bounds__(256) void transpose_xp(
    const float* __restrict__ xp, float* __restrict__ xpt)
{
    __shared__ float tile[NB][33];     // [b][g] padded
    int t  = blockIdx.x;
    int g0 = blockIdx.y * 32;
    int tx = threadIdx.x & 31;         // g (read) / b (write)
    int ty = threadIdx.x >> 5;         // 8 rows

    // read: for each b, 32 consecutive g (coalesced)
    for (int b = ty; b < NB; b += 8)
        tile[b][tx] = xp[((size_t)b * TT + t) * H3 + g0 + tx];
    __syncthreads();

    // write: for each g, 100 consecutive b (coalesced)
    for (int gi = ty; gi < 32; gi += 8) {
        size_t base = ((size_t)t * H3 + g0 + gi) * NB;
#pragma unroll
        for (int c = 0; c < 4; c++) {
            int b = c * 32 + tx;
            if (b < NB) xpt[base + b] = tile[b][gi];
        }
    }
}

// =================================================================
// Persistent GRU v2. 128 blocks x 400 threads (12.5 warps).
// Block owns 8 cols; Whh duplicated f32x2 in smem (196KB).
// Thread = 1 col x 2 batches. Grid barrier between steps.
// =================================================================
__device__ __forceinline__ void gridbar()
{
    __threadfence();
    __syncthreads();
    if (threadIdx.x == 0) {
        volatile unsigned* vg = &g_gen;
        unsigned target = *vg + 1;
        if (atomicAdd(&g_cnt, 1) == gridDim.x - 1) {
            g_cnt = 0;
            __threadfence();
            atomicAdd(&g_gen, 1);
        } else {
            while ((int)(*vg - target) < 0) { }
        }
        __threadfence();
    }
    __syncthreads();
}

__global__ __launch_bounds__(400, 1) void gru_persist(
    const float* __restrict__ xpt, const float* __restrict__ Whh,
    const float* __restrict__ bhh, float* __restrict__ hst)
{
    extern __shared__ u64 swd[];   // [8 cols][3 gates][1024] duplicated pairs
    int tid  = threadIdx.x;
    int colL = tid / 50;           // 0..7
    int bp   = tid % 50;           // batches 2bp, 2bp+1
    int c    = blockIdx.x * 8 + colL;

    for (int i = tid; i < 8 * 3 * 256; i += 400) {
        int cl = i / 768, rem = i % 768, g = rem / 256, k4 = rem % 256;
        float4 w = *(const float4*)(Whh + ((size_t)g * HD + blockIdx.x * 8 + cl) * HD + k4 * 4);
        u64* dst = &swd[(size_t)(cl * 3 + g) * 1024 + k4 * 4];
        dst[0] = bcast2(w.x); dst[1] = bcast2(w.y); dst[2] = bcast2(w.z); dst[3] = bcast2(w.w);
    }
    float br = bhh[c], bz = bhh[HD + c], bn = bhh[2 * HD + c];
    __syncthreads();

    const u64* wr = &swd[(size_t)(colL * 3 + 0) * 1024];
    const u64* wz = &swd[(size_t)(colL * 3 + 1) * 1024];
    const u64* wn = &swd[(size_t)(colL * 3 + 2) * 1024];

    for (int t = 0; t < TT; t++) {
        u64 ar = 0, az = 0, an = 0;
        float2 hold = make_float2(0.f, 0.f);
        if (t > 0) {
            const float* hp = hst + (size_t)(t - 1) * NDB + 2 * bp;
            hold = *(const float2*)(hp + (size_t)c * NB);
#pragma unroll 1
            for (int k0 = 0; k0 < HD; k0 += 8) {
                u64 h[8];
#pragma unroll
                for (int j = 0; j < 8; j++)
                    h[j] = *(const u64*)(hp + (size_t)(k0 + j) * NB);
                ulonglong2 r0 = *(const ulonglong2*)(wr + k0);
                ulonglong2 r1 = *(const ulonglong2*)(wr + k0 + 2);
                ulonglong2 r2 = *(const ulonglong2*)(wr + k0 + 4);
                ulonglong2 r3 = *(const ulonglong2*)(wr + k0 + 6);
                ulonglong2 z0 = *(const ulonglong2*)(wz + k0);
                ulonglong2 z1 = *(const ulonglong2*)(wz + k0 + 2);
                ulonglong2 z2 = *(const ulonglong2*)(wz + k0 + 4);
                ulonglong2 z3 = *(const ulonglong2*)(wz + k0 + 6);
                ulonglong2 n0 = *(const ulonglong2*)(wn + k0);
                ulonglong2 n1 = *(const ulonglong2*)(wn + k0 + 2);
                ulonglong2 n2 = *(const ulonglong2*)(wn + k0 + 4);
                ulonglong2 n3 = *(const ulonglong2*)(wn + k0 + 6);
                fma2(ar, r0.x, h[0]); fma2(az, z0.x, h[0]); fma2(an, n0.x, h[0]);
                fma2(ar, r0.y, h[1]); fma2(az, z0.y, h[1]); fma2(an, n0.y, h[1]);
                fma2(ar, r1.x, h[2]); fma2(az, z1.x, h[2]); fma2(an, n1.x, h[2]);
                fma2(ar, r1.y, h[3]); fma2(az, z1.y, h[3]); fma2(an, n1.y, h[3]);
                fma2(ar, r2.x, h[4]); fma2(az, z2.x, h[4]); fma2(an, n2.x, h[4]);
                fma2(ar, r2.y, h[5]); fma2(az, z2.y, h[5]); fma2(an, n2.y, h[5]);
                fma2(ar, r3.x, h[6]); fma2(az, z3.x, h[6]); fma2(an, n3.x, h[6]);
                fma2(ar, r3.y, h[7]); fma2(az, z3.y, h[7]); fma2(an, n3.y, h[7]);
            }
        }
        float2 pr = unpk(ar), pz = unpk(az), pn = unpk(an);

        size_t xb = ((size_t)t * H3) * NB + 2 * bp;
        float2 xr = *(const float2*)(xpt + xb + (size_t)c * NB);
        float2 xz = *(const float2*)(xpt + xb + (size_t)(HD + c) * NB);
        float2 xn = *(const float2*)(xpt + xb + (size_t)(2 * HD + c) * NB);

        float rr0 = sigf(xr.x + pr.x + br);
        float zz0 = sigf(xz.x + pz.x + bz);
        float nn0 = tanhf(xn.x + rr0 * (pn.x + bn));
        float h0  = (1.f - zz0) * nn0 + zz0 * hold.x;

        float rr1 = sigf(xr.y + pr.y + br);
        float zz1 = sigf(xz.y + pz.y + bz);
        float nn1 = tanhf(xn.y + rr1 * (pn.y + bn));
        float h1  = (1.f - zz1) * nn1 + zz1 * hold.y;

        *(float2*)(hst + (size_t)t * NDB + (size_t)c * NB + 2 * bp) = make_float2(h0, h1);

        gridbar();
    }
}

// =================================================================
// one-pass online-softmax reduce: vt[j] = sum_u softmax_u(S[u,j]) H[u,j]
// =================================================================
__global__ void att_reduce_flat(const float* __restrict__ S,
                                const float* __restrict__ H,
                                float* __restrict__ vt)
{
    int j = blockIdx.x * 256 + threadIdx.x;
    float mx = -1e30f, se = 0.f, sv = 0.f;
#pragma unroll 4
    for (int u = 0; u < TT; u++) {
        float s = S[(size_t)u * NDB + j];
        float h = H[(size_t)u * NDB + j];
        float m2 = fmaxf(mx, s);
        float cor = expf(mx - m2);
        float e = expf(s - m2);
        se = se * cor + e;
        sv = sv * cor + e * h;
        mx = m2;
    }
    vt[j] = sv / se;
}

// pool attention on vt[d][b] -> catv8[d*8 + c]
__global__ void pool_att_t(const float* __restrict__ vt, const float* __restrict__ pW,
                           const float* __restrict__ pb, float* __restrict__ catv8)
{
    int c = blockIdx.x;
    int d = blockIdx.y * 256 + threadIdx.x;
    if (c >= 5) { catv8[(size_t)d * 8 + c] = 0.f; return; }
    __shared__ float sW[400];
    __shared__ float sb[20];
    for (int i = threadIdx.x; i < 400; i += 256) sW[i] = pW[i];
    if (threadIdx.x < 20) sb[threadIdx.x] = pb[threadIdx.x];
    __syncthreads();

    float xv[20];
#pragma unroll
    for (int s = 0; s < 20; s++) xv[s] = vt[(size_t)d * NB + c * 20 + s];
    float wv[20]; float mx = -1e30f;
#pragma unroll
    for (int u = 0; u < 20; u++) {
        float s = sb[u];
#pragma unroll
        for (int t2 = 0; t2 < 20; t2++) s += xv[t2] * sW[u * 20 + t2];
        wv[u] = s; mx = fmaxf(mx, s);
    }
    float se = 0.f, sv = 0.f;
#pragma unroll
    for (int u = 0; u < 20; u++) {
        float e = expf(wv[u] - mx);
        se += e; sv += e * xv[u];
    }
    catv8[(size_t)d * 8 + c] = sv / se;
}

// two dots per node on [j][stride] layout
__global__ void dot2_t(const float* __restrict__ ht, const float* __restrict__ a1,
                       const float* __restrict__ a2, float* __restrict__ o1,
                       float* __restrict__ o2, int stride)
{
    int n = blockIdx.x;
    __shared__ float s1[256], s2[256];
    float p1 = 0.f, p2 = 0.f;
    for (int j = threadIdx.x; j < HD; j += 256) {
        float hv = ht[(size_t)j * stride + n];
        p1 += hv * a1[j]; p2 += hv * a2[j];
    }
    s1[threadIdx.x] = p1; s2[threadIdx.x] = p2;
    __syncthreads();
    for (int s = 128; s > 0; s >>= 1) {
        if (threadIdx.x < s) { s1[threadIdx.x] += s1[threadIdx.x + s]; s2[threadIdx.x] += s2[threadIdx.x + s]; }
        __syncthreads();
    }
    if (threadIdx.x == 0) { o1[n] = s1[0]; o2[n] = s2[0]; }
}

// GAT aggregation on [j][stride] layout (complete cliques + self loops)
__global__ void gat_agg_t(const float* __restrict__ ht, const float* __restrict__ as,
                          const float* __restrict__ ad, const float* __restrict__ bias,
                          float* __restrict__ outt, int group, int stride, int ostride)
{
    int n = blockIdx.x;
    int base = (n / group) * group;
    __shared__ float alpha[32];
    if (threadIdx.x == 0) {
        float e[32]; float mx = -1e30f;
        for (int s = 0; s < group; s++) {
            float x = as[base + s] + ad[n];
            x = (x > 0.f) ? x : 0.2f * x;
            e[s] = x; mx = fmaxf(mx, x);
        }
        float se = 0.f;
        for (int s = 0; s < group; s++) { e[s] = expf(e[s] - mx); se += e[s]; }
        for (int s = 0; s < group; s++) alpha[s] = e[s] / se;
    }
    __syncthreads();
    for (int j = threadIdx.x; j < HD; j += 256) {
        float acc = 0.f;
        for (int s = 0; s < group; s++)
            acc += alpha[s] * ht[(size_t)j * stride + base + s];
        outt[(size_t)j * ostride + n] = acc + bias[j];
    }
}

// fusion concat into fint[k][n]
__global__ void build_fusion_t(const float* __restrict__ vt, const float* __restrict__ catot,
                               const float* __restrict__ innert, float* __restrict__ fint)
{
    int idx = blockIdx.x * 256 + threadIdx.x;
    if (idx >= H3 * NB) return;
    int k = idx / NB, n = idx - k * NB;
    float val;
    if (k < HD)            val = vt[(size_t)k * NB + n];
    else if (k < 2 * HD)   val = catot[(size_t)(k - HD) * 5 + n / 20];
    else                   val = innert[(size_t)(k - 2 * HD) * NB + n];
    fint[idx] = val;
}

// heads on ft[j][n]
__global__ void heads_t(const float* __restrict__ ft, const float* __restrict__ rw,
                        const float* __restrict__ rb, const float* __restrict__ cw,
                        const float* __restrict__ cb, float* __restrict__ out)
{
    int n = blockIdx.x;
    __shared__ float s1[256], s2[256];
    float p1 = 0.f, p2 = 0.f;
    for (int j = threadIdx.x; j < HD; j += 256) {
        float fv = ft[(size_t)j * NB + n];
        p1 += fv * rw[j]; p2 += fv * cw[j];
    }
    s1[threadIdx.x] = p1; s2[threadIdx.x] = p2;
    __syncthreads();
    for (int s = 128; s > 0; s >>= 1) {
        if (threadIdx.x < s) { s1[threadIdx.x] += s1[threadIdx.x + s]; s2[threadIdx.x] += s2[threadIdx.x + s]; }
        __syncthreads();
    }
    if (threadIdx.x == 0) {
        out[n]      = s1[0] + rb[0];
        out[NB + n] = 1.f / (1.f + expf(-(s2[0] + cb[0])));
    }
}

// =================================================================
extern "C" void kernel_launch(void* const* d_in, const int* in_sizes, int n_in,
                              void* d_out, int out_size)
{
    const float* weekly  = (const float*)d_in[0];
    const float* Wih     = (const float*)d_in[1];
    const float* Whh     = (const float*)d_in[2];
    const float* bih     = (const float*)d_in[3];
    const float* bhh     = (const float*)d_in[4];
    const float* encW    = (const float*)d_in[5];
    const float* encB    = (const float*)d_in[6];
    const float* poolW   = (const float*)d_in[7];
    const float* poolB   = (const float*)d_in[8];
    const float* innerW  = (const float*)d_in[9];
    const float* innerAs = (const float*)d_in[10];
    const float* innerAd = (const float*)d_in[11];
    const float* innerB  = (const float*)d_in[12];
    const float* catW    = (const float*)d_in[13];
    const float* catAs   = (const float*)d_in[14];
    const float* catAd   = (const float*)d_in[15];
    const float* catB    = (const float*)d_in[16];
    const float* fusW    = (const float*)d_in[17];
    const float* fusB    = (const float*)d_in[18];
    const float* regW    = (const float*)d_in[19];
    const float* regB    = (const float*)d_in[20];
    const float* clsW    = (const float*)d_in[21];
    const float* clsB    = (const float*)d_in[22];
    float* out = (float*)d_out;

    float *xp, *xpt, *hst, *vt, *hpt, *innert, *catv8, *hp2t, *catot, *as_, *ad_, *as2, *ad2, *fint, *ftb;
    cudaGetSymbolAddress((void**)&xp,     g_xp);
    cudaGetSymbolAddress((void**)&xpt,    g_xpt);
    cudaGetSymbolAddress((void**)&hst,    g_hst);
    cudaGetSymbolAddress((void**)&vt,     g_vt);
    cudaGetSymbolAddress((void**)&hpt,    g_hpt);
    cudaGetSymbolAddress((void**)&innert, g_innert);
    cudaGetSymbolAddress((void**)&catv8,  g_catv8);
    cudaGetSymbolAddress((void**)&hp2t,   g_hp2t);
    cudaGetSymbolAddress((void**)&catot,  g_catot);
    cudaGetSymbolAddress((void**)&as_,    g_as);
    cudaGetSymbolAddress((void**)&ad_,    g_ad);
    cudaGetSymbolAddress((void**)&as2,    g_as2);
    cudaGetSymbolAddress((void**)&ad2,    g_ad2);
    cudaGetSymbolAddress((void**)&fint,   g_fint);
    cudaGetSymbolAddress((void**)&ftb,    g_ft);

    // 1) xp = weekly(51200,256) @ Wih^T + bih
    gemm_nt<<<dim3(H3 / 128, (NB * TT) / 128), 256>>>(weekly, Wih, bih, xp, NB * TT, H3, IND, 0);

    // 1b) transpose to xpt[t][g][b] for coalesced GRU access
    transpose_xp<<<dim3(TT, H3 / 32), 256>>>(xp, xpt);

    // 2) persistent GRU (all 512 steps in one launch)
    cudaFuncSetAttribute(gru_persist, cudaFuncAttributeMaxDynamicSharedMemorySize, 196608);
    gru_persist<<<128, 400, 196608>>>(xpt, Whh, bhh, hst);

    // 3) S(512 x 102400) = encW @ H + encB[u]  (reuse xp buffer)
    gemm_nn<<<dim3(NDB / 128, TT / 128), 256>>>(encW, hst, encB, xp, TT, NDB, TT, 0);

    // 4) vt[j] = softmax-over-u(S) . H  (single pass)
    att_reduce_flat<<<NDB / 256, 256>>>(xp, hst, vt);

    // 5) inner GAT: hpt = innerW @ vt
    gemm_nn<<<dim3(1, HD / 128), 256>>>(innerW, vt, nullptr, hpt, HD, NB, HD, 0);
    dot2_t<<<NB, 256>>>(hpt, innerAs, innerAd, as_, ad_, NB);
    gat_agg_t<<<NB, 256>>>(hpt, as_, ad_, innerB, innert, 20, NB, NB);

    // 6) pool 20 stocks -> category vectors (padded to stride 8)
    pool_att_t<<<dim3(8, HD / 256), 256>>>(vt, poolW, poolB, catv8);

    // 7) category GAT
    gemm_nn<<<dim3(1, HD / 128), 256>>>(catW, catv8, nullptr, hp2t, HD, 8, HD, 0);
    dot2_t<<<5, 256>>>(hp2t, catAs, catAd, as2, ad2, 8);
    gat_agg_t<<<5, 256>>>(hp2t, as2, ad2, catB, catot, 5, 8, 5);

    // 8) fusion
    build_fusion_t<<<(H3 * NB + 255) / 256, 256>>>(vt, catot, innert, fint);
    gemm_nn<<<dim3(1, HD / 128), 256>>>(fusW, fint, fusB, ftb, HD, NB, H3, 1);

    // 9) heads
    heads_t<<<NB, 256>>>(ftb, regW, regB, clsW, clsB, out);
}